// round 5
// baseline (speedup 1.0000x reference)
#include <cuda_runtime.h>
#include <cuda_bf16.h>

#define NP      20
#define D       64
#define NROWS   16384
#define EPS2    1e-24f          // (1e-12)^2 under rsqrt

// scratch for normalized query vectors z[n][64]  (static device global: allowed)
__device__ float g_z[NROWS * D];

// packed f32x2 fma: acc = a*b + acc (element-wise on packed pairs)
__device__ __forceinline__ void fma2(unsigned long long& acc,
                                     unsigned long long a,
                                     unsigned long long b) {
    asm("fma.rn.f32x2 %0, %1, %2, %0;" : "+l"(acc) : "l"(a), "l"(b));
}

// ============================================================================
// Kernel B: z = normalize(x @ W^T + b)   (compute-bound, small)
// ============================================================================
#define B_R       4
#define B_WPB     8
#define B_THREADS 256
#define B_ROWSB   (B_WPB * B_R)          // 32
#define B_NBLOCKS (NROWS / B_ROWSB)      // 512

__global__ __launch_bounds__(B_THREADS)
void matvec_norm_kernel(const float* __restrict__ x,
                        const float* __restrict__ W,
                        const float* __restrict__ b)
{
    __shared__ float2 Wp[D / 2][D];      // Wp[kk][d] = {W[d][2kk], W[d][2kk+1]}
    __shared__ float  xs[B_ROWSB][D];

    const int tid  = threadIdx.x;
    const int warp = tid >> 5;
    const int lane = tid & 31;
    const int rowbase = (blockIdx.x * B_WPB + warp) * B_R;
    const int rl      = warp * B_R;

    // stage W as k-pair / dim tiles (coalesced float2 reads of W rows)
    #pragma unroll
    for (int i = tid; i < D * D / 2; i += B_THREADS) {
        int d = i >> 5, kk = i & 31;                 // i == d*32 + kk
        Wp[kk][d] = ((const float2*)W)[i];
    }
    // stage x rows
    #pragma unroll
    for (int r = 0; r < B_R; ++r) {
        float2 v = ((const float2*)(x + (size_t)(rowbase + r) * D))[lane];
        ((float2*)&xs[rl + r][0])[lane] = v;
    }
    __syncthreads();

    // lane owns dims (2*lane, 2*lane+1); accumulate even-k/odd-k partials packed
    unsigned long long h0[B_R], h1[B_R];
    #pragma unroll
    for (int r = 0; r < B_R; ++r) { h0[r] = 0ull; h1[r] = 0ull; }

    #pragma unroll 8
    for (int kk = 0; kk < D / 2; ++kk) {
        // both dim-pairs' weights in one LDS.128 (16B aligned, conflict-free)
        ulonglong2 wv = *(const ulonglong2*)&Wp[kk][2 * lane];
        #pragma unroll
        for (int r = 0; r < B_R; ++r) {
            unsigned long long xp =
                *(const unsigned long long*)&xs[rl + r][2 * kk];   // broadcast
            fma2(h0[r], xp, wv.x);
            fma2(h1[r], xp, wv.y);
        }
    }

    const float2 bb = ((const float2*)b)[lane];

    #pragma unroll
    for (int r = 0; r < B_R; ++r) {
        float2 p0 = *(float2*)&h0[r];
        float2 p1 = *(float2*)&h1[r];
        float hx = p0.x + p0.y + bb.x;
        float hy = p1.x + p1.y + bb.y;

        float nn = hx * hx + hy * hy;
        #pragma unroll
        for (int m = 16; m >= 1; m >>= 1)
            nn += __shfl_xor_sync(0xFFFFFFFFu, nn, m);
        float inv = rsqrtf(fmaxf(nn, EPS2));

        float2 zv = make_float2(hx * inv, hy * inv);
        ((float2*)(g_z + (size_t)(rowbase + r) * D))[lane] = zv;   // coalesced
    }
}

// ============================================================================
// Kernel A: out[row] = z[row] . sum_p normalize(proto[uidx[row]][p])
//           1 warp per row; all 10 chunk loads in flight (pure DRAM streamer)
// ============================================================================
#define A_WPB     8
#define A_THREADS 256
#define A_NBLOCKS (NROWS / A_WPB)        // 2048

__global__ __launch_bounds__(A_THREADS)
void gather_score_kernel(const int* __restrict__ uidx,
                         const float* __restrict__ proto,
                         float* __restrict__ out)
{
    const int tid  = threadIdx.x;
    const int warp = tid >> 5;
    const int lane = tid & 31;
    const int q    = lane & 15;          // float4 slot within a proto
    const int half = lane >> 4;          // which proto of each pair

    const int row = blockIdx.x * A_WPB + warp;

    const int u = __ldg(&uidx[row]);
    const float4* base =
        (const float4*)(proto + (size_t)u * (NP * D)) + half * (D / 4) + q;

    // issue ALL anchor loads up front — 10 independent LDG.128 per lane
    float4 a[NP / 2];
    #pragma unroll
    for (int c = 0; c < NP / 2; ++c)
        a[c] = __ldg(base + c * (2 * D / 4));

    const float4 zq = __ldg((const float4*)(g_z + (size_t)row * D) + q);

    float4 s = make_float4(0.f, 0.f, 0.f, 0.f);
    #pragma unroll
    for (int c = 0; c < NP / 2; ++c) {
        float nn = a[c].x * a[c].x + a[c].y * a[c].y
                 + a[c].z * a[c].z + a[c].w * a[c].w;
        #pragma unroll
        for (int m = 8; m >= 1; m >>= 1)
            nn += __shfl_xor_sync(0xFFFFFFFFu, nn, m);     // 16-lane reduce
        float inv = rsqrtf(fmaxf(nn, EPS2));
        s.x = fmaf(a[c].x, inv, s.x);
        s.y = fmaf(a[c].y, inv, s.y);
        s.z = fmaf(a[c].z, inv, s.z);
        s.w = fmaf(a[c].w, inv, s.w);
    }

    // z . (s_half0 + s_half1): each half dots its own s; 32-lane reduce sums both
    float d = zq.x * s.x + zq.y * s.y + zq.z * s.z + zq.w * s.w;
    #pragma unroll
    for (int m = 16; m >= 1; m >>= 1)
        d += __shfl_xor_sync(0xFFFFFFFFu, d, m);

    if (lane == 0)
        out[row] = d;
}

// ============================================================================
extern "C" void kernel_launch(void* const* d_in, const int* in_sizes, int n_in,
                              void* d_out, int out_size) {
    const int*   uidx  = (const int*)d_in[0];
    const float* x     = (const float*)d_in[1];
    const float* proto = (const float*)d_in[2];
    const float* W     = (const float*)d_in[3];
    const float* b     = (const float*)d_in[4];
    float* out = (float*)d_out;

    matvec_norm_kernel<<<B_NBLOCKS, B_THREADS>>>(x, W, b);
    gather_score_kernel<<<A_NBLOCKS, A_THREADS>>>(uidx, proto, out);
}